// round 1
// baseline (speedup 1.0000x reference)
#include <cuda_runtime.h>

#define EPSF 1e-12f

// Problem constants: N=8, T=2048, D=512, K=64, M=N*T=16384
// Scratch (device globals; no allocation allowed)
__device__ float g_a[16384 * 64];     // a' = softmax * inv_norm, [m][k]   (4 MB)
__device__ float g_asum[512];         // sum_t a[n,t,k]  (NOT scaled by inv) [n][k]
__device__ float g_vlad[262144];      // accumulation sum_t a'*x, [n][k][d] (1 MB)
__device__ float g_gsum[8];           // per-n global sum of squares after intra-norm

// ---------------------------------------------------------------------------
// K0: zero the accumulators (d_out is poisoned; scratch must be zeroed every call)
// ---------------------------------------------------------------------------
__global__ void zero_kernel() {
    int i = blockIdx.x * 256 + threadIdx.x;
    if (i < 262144) g_vlad[i] = 0.f;
    if (i < 512)    g_asum[i] = 0.f;
    if (i < 8)      g_gsum[i] = 0.f;
}

// ---------------------------------------------------------------------------
// K1: fused  row-L2-norm  +  logits GEMM (x @ W^T + b)  +  softmax over K
//     Stores a' = a * inv_norm(row) into g_a, accumulates asum (of a) per (n,k).
// Block: 256 threads, tile M=64 rows x K=64 clusters, reduce D=512 in 32-chunks.
// Each thread computes a 4x4 micro-tile. Thread (tx,ty): tx=cols(k), ty=rows(m).
// ---------------------------------------------------------------------------
__global__ __launch_bounds__(256) void logits_kernel(
        const float* __restrict__ x, const float* __restrict__ W,
        const float* __restrict__ bias) {
    __shared__ float As[32][68];   // x tile, [kk][row]  (+4 pad: conflict-free)
    __shared__ float Bs[32][68];   // W tile, [kk][col]
    __shared__ float rowinv[64];
    __shared__ float sbias[64];
    __shared__ float sAsum[64];

    const int tid = threadIdx.x;
    const int m0  = blockIdx.x * 64;          // 256 blocks cover M=16384
    const int tx  = tid & 15;
    const int ty  = tid >> 4;

    if (tid < 64) { sbias[tid] = bias[tid]; sAsum[tid] = 0.f; }

    // loader mapping: each thread always loads the SAME row (tid>>2),
    // 8 consecutive k's at offset (tid&3)*8 -> thread sees 1/4 of its row
    // across the k-loop, so the row sum-of-squares is a 4-lane shuffle reduce.
    const int lrow = tid >> 2;
    const int lkk  = (tid & 3) * 8;
    const float* xrow = x + (size_t)(m0 + lrow) * 512 + lkk;
    const float* wrow = W + (size_t)lrow * 512 + lkk;   // lrow doubles as cluster col

    float acc[4][4];
#pragma unroll
    for (int i = 0; i < 4; i++)
#pragma unroll
        for (int j = 0; j < 4; j++) acc[i][j] = 0.f;
    float sq = 0.f;

    for (int kb = 0; kb < 512; kb += 32) {
        float4 a0 = *(const float4*)(xrow + kb);
        float4 a1 = *(const float4*)(xrow + kb + 4);
        float4 b0 = *(const float4*)(wrow + kb);
        float4 b1 = *(const float4*)(wrow + kb + 4);
        sq += a0.x*a0.x + a0.y*a0.y + a0.z*a0.z + a0.w*a0.w
            + a1.x*a1.x + a1.y*a1.y + a1.z*a1.z + a1.w*a1.w;
        __syncthreads();
        As[lkk+0][lrow]=a0.x; As[lkk+1][lrow]=a0.y; As[lkk+2][lrow]=a0.z; As[lkk+3][lrow]=a0.w;
        As[lkk+4][lrow]=a1.x; As[lkk+5][lrow]=a1.y; As[lkk+6][lrow]=a1.z; As[lkk+7][lrow]=a1.w;
        Bs[lkk+0][lrow]=b0.x; Bs[lkk+1][lrow]=b0.y; Bs[lkk+2][lrow]=b0.z; Bs[lkk+3][lrow]=b0.w;
        Bs[lkk+4][lrow]=b1.x; Bs[lkk+5][lrow]=b1.y; Bs[lkk+6][lrow]=b1.z; Bs[lkk+7][lrow]=b1.w;
        __syncthreads();
#pragma unroll
        for (int kk = 0; kk < 32; kk++) {
            float4 av = *(const float4*)&As[kk][ty * 4];
            float4 bv = *(const float4*)&Bs[kk][tx * 4];
            acc[0][0] += av.x*bv.x; acc[0][1] += av.x*bv.y; acc[0][2] += av.x*bv.z; acc[0][3] += av.x*bv.w;
            acc[1][0] += av.y*bv.x; acc[1][1] += av.y*bv.y; acc[1][2] += av.y*bv.z; acc[1][3] += av.y*bv.w;
            acc[2][0] += av.z*bv.x; acc[2][1] += av.z*bv.y; acc[2][2] += av.z*bv.z; acc[2][3] += av.z*bv.w;
            acc[3][0] += av.w*bv.x; acc[3][1] += av.w*bv.y; acc[3][2] += av.w*bv.z; acc[3][3] += av.w*bv.w;
        }
    }

    // per-row inverse norm (4 consecutive lanes own one row)
    sq += __shfl_xor_sync(0xffffffffu, sq, 1);
    sq += __shfl_xor_sync(0xffffffffu, sq, 2);
    if ((tid & 3) == 0) rowinv[lrow] = 1.f / fmaxf(sqrtf(sq), EPSF);
    __syncthreads();

    // softmax over K (row of 64 spread across 16 lanes with same ty)
    float colsum[4] = {0.f, 0.f, 0.f, 0.f};
#pragma unroll
    for (int i = 0; i < 4; i++) {
        const int r = ty * 4 + i;
        const float inv = rowinv[r];
        float l0 = acc[i][0]*inv + sbias[tx*4+0];
        float l1 = acc[i][1]*inv + sbias[tx*4+1];
        float l2 = acc[i][2]*inv + sbias[tx*4+2];
        float l3 = acc[i][3]*inv + sbias[tx*4+3];
        float mx = fmaxf(fmaxf(l0, l1), fmaxf(l2, l3));
        mx = fmaxf(mx, __shfl_xor_sync(0xffffffffu, mx, 8));
        mx = fmaxf(mx, __shfl_xor_sync(0xffffffffu, mx, 4));
        mx = fmaxf(mx, __shfl_xor_sync(0xffffffffu, mx, 2));
        mx = fmaxf(mx, __shfl_xor_sync(0xffffffffu, mx, 1));
        float e0 = __expf(l0 - mx), e1 = __expf(l1 - mx);
        float e2 = __expf(l2 - mx), e3 = __expf(l3 - mx);
        float sm = e0 + e1 + e2 + e3;
        sm += __shfl_xor_sync(0xffffffffu, sm, 8);
        sm += __shfl_xor_sync(0xffffffffu, sm, 4);
        sm += __shfl_xor_sync(0xffffffffu, sm, 2);
        sm += __shfl_xor_sync(0xffffffffu, sm, 1);
        float rcp = 1.f / sm;
        float a0v = e0 * rcp, a1v = e1 * rcp, a2v = e2 * rcp, a3v = e3 * rcp;
        colsum[0] += a0v; colsum[1] += a1v; colsum[2] += a2v; colsum[3] += a3v;
        // store a' = a * inv  (folds l2-normalization of x into the VLAD GEMM)
        float4 st;
        st.x = a0v * inv; st.y = a1v * inv; st.z = a2v * inv; st.w = a3v * inv;
        *(float4*)(g_a + (size_t)(m0 + r) * 64 + tx * 4) = st;
    }
    atomicAdd(&sAsum[tx*4+0], colsum[0]);
    atomicAdd(&sAsum[tx*4+1], colsum[1]);
    atomicAdd(&sAsum[tx*4+2], colsum[2]);
    atomicAdd(&sAsum[tx*4+3], colsum[3]);
    __syncthreads();
    if (tid < 64) atomicAdd(&g_asum[(m0 >> 11) * 64 + tid], sAsum[tid]);
}

// ---------------------------------------------------------------------------
// K2: VLAD accumulation   g_vlad[n,k,d] += sum_t a'[n,t,k] * x[n,t,d]
// Per block: 64 clusters x 64 d-cols, reduce 512 t's (split T=2048 into 4).
// Grid: (8 d-tiles, 4 T-splits, 8 n) = 256 blocks.
// ---------------------------------------------------------------------------
__global__ __launch_bounds__(256) void vlad_kernel(const float* __restrict__ x) {
    __shared__ float As[32][68];   // a'[tt][k]
    __shared__ float Xs[32][68];   // x [tt][d]

    const int tid = threadIdx.x;
    const int tx  = tid & 15;
    const int ty  = tid >> 4;
    const int d0  = blockIdx.x * 64;
    const int n   = blockIdx.z;
    const int tb  = blockIdx.y * 512;

    const int ltt = tid >> 3;            // 0..31
    const int lc  = (tid & 7) * 8;       // 0..56
    const float* abase = g_a + ((size_t)n * 2048 + tb + ltt) * 64 + lc;
    const float* xbase = x   + ((size_t)n * 2048 + tb + ltt) * 512 + d0 + lc;

    float acc[4][4];
#pragma unroll
    for (int i = 0; i < 4; i++)
#pragma unroll
        for (int j = 0; j < 4; j++) acc[i][j] = 0.f;

    for (int t0 = 0; t0 < 512; t0 += 32) {
        float4 a0 = *(const float4*)(abase + (size_t)t0 * 64);
        float4 a1 = *(const float4*)(abase + (size_t)t0 * 64 + 4);
        float4 x0 = *(const float4*)(xbase + (size_t)t0 * 512);
        float4 x1 = *(const float4*)(xbase + (size_t)t0 * 512 + 4);
        __syncthreads();
        As[ltt][lc+0]=a0.x; As[ltt][lc+1]=a0.y; As[ltt][lc+2]=a0.z; As[ltt][lc+3]=a0.w;
        As[ltt][lc+4]=a1.x; As[ltt][lc+5]=a1.y; As[ltt][lc+6]=a1.z; As[ltt][lc+7]=a1.w;
        Xs[ltt][lc+0]=x0.x; Xs[ltt][lc+1]=x0.y; Xs[ltt][lc+2]=x0.z; Xs[ltt][lc+3]=x0.w;
        Xs[ltt][lc+4]=x1.x; Xs[ltt][lc+5]=x1.y; Xs[ltt][lc+6]=x1.z; Xs[ltt][lc+7]=x1.w;
        __syncthreads();
#pragma unroll
        for (int tt = 0; tt < 32; tt++) {
            float4 av = *(const float4*)&As[tt][ty * 4];
            float4 xv = *(const float4*)&Xs[tt][tx * 4];
            acc[0][0] += av.x*xv.x; acc[0][1] += av.x*xv.y; acc[0][2] += av.x*xv.z; acc[0][3] += av.x*xv.w;
            acc[1][0] += av.y*xv.x; acc[1][1] += av.y*xv.y; acc[1][2] += av.y*xv.z; acc[1][3] += av.y*xv.w;
            acc[2][0] += av.z*xv.x; acc[2][1] += av.z*xv.y; acc[2][2] += av.z*xv.z; acc[2][3] += av.z*xv.w;
            acc[3][0] += av.w*xv.x; acc[3][1] += av.w*xv.y; acc[3][2] += av.w*xv.z; acc[3][3] += av.w*xv.w;
        }
    }

    float* vbase = g_vlad + (size_t)n * 32768 + d0;
#pragma unroll
    for (int i = 0; i < 4; i++)
#pragma unroll
        for (int j = 0; j < 4; j++)
            atomicAdd(&vbase[(size_t)(ty*4 + i) * 512 + tx*4 + j], acc[i][j]);
}

// ---------------------------------------------------------------------------
// K3: finalize per (n,k): v = vlad - asum*c, intra L2 normalize, write out,
//     accumulate global sum of squares per n.
// ---------------------------------------------------------------------------
__global__ __launch_bounds__(128) void finalize_kernel(
        const float* __restrict__ cent, float* __restrict__ out) {
    __shared__ float red[4];
    const int row = blockIdx.x;      // 0..511 = n*64+k
    const int k   = row & 63;
    const int n   = row >> 6;
    const int t   = threadIdx.x;     // 128 threads x float4 = 512

    const float s = g_asum[row];
    float4 v = ((const float4*)(g_vlad + (size_t)row * 512))[t];
    float4 c = ((const float4*)(cent   + (size_t)k   * 512))[t];
    v.x -= s * c.x; v.y -= s * c.y; v.z -= s * c.z; v.w -= s * c.w;

    float sq = v.x*v.x + v.y*v.y + v.z*v.z + v.w*v.w;
#pragma unroll
    for (int o = 16; o > 0; o >>= 1) sq += __shfl_xor_sync(0xffffffffu, sq, o);
    if ((t & 31) == 0) red[t >> 5] = sq;
    __syncthreads();
    const float tot = red[0] + red[1] + red[2] + red[3];
    const float inv = 1.f / fmaxf(sqrtf(tot), EPSF);

    float4 o4;
    o4.x = v.x * inv; o4.y = v.y * inv; o4.z = v.z * inv; o4.w = v.w * inv;
    ((float4*)(out + (size_t)row * 512))[t] = o4;

    if (t == 0) atomicAdd(&g_gsum[n], tot * inv * inv);
}

// ---------------------------------------------------------------------------
// K4: global L2 normalize per n
// ---------------------------------------------------------------------------
__global__ __launch_bounds__(128) void scale_kernel(float* __restrict__ out) {
    const int n = blockIdx.x >> 6;   // 64 blocks per n
    const float inv = 1.f / fmaxf(sqrtf(g_gsum[n]), EPSF);
    float4* p = (float4*)out + (size_t)blockIdx.x * 128 + threadIdx.x;
    float4 v = *p;
    v.x *= inv; v.y *= inv; v.z *= inv; v.w *= inv;
    *p = v;
}

// ---------------------------------------------------------------------------
extern "C" void kernel_launch(void* const* d_in, const int* in_sizes, int n_in,
                              void* d_out, int out_size) {
    const float* x    = (const float*)d_in[0];   // [8,2048,512]
    const float* W    = (const float*)d_in[1];   // [64,512]
    const float* b    = (const float*)d_in[2];   // [64]
    const float* cent = (const float*)d_in[3];   // [64,512]
    float* out = (float*)d_out;                  // [8, 64*512]

    zero_kernel<<<1024, 256>>>();
    logits_kernel<<<256, 256>>>(x, W, b);
    vlad_kernel<<<dim3(8, 4, 8), 256>>>(x);
    finalize_kernel<<<512, 128>>>(cent, out);
    scale_kernel<<<512, 128>>>(out);
}

// round 2
// speedup vs baseline: 1.5854x; 1.5854x over previous
#include <cuda_runtime.h>
#include <cuda_bf16.h>
#include <cstdint>

#define EPSF 1e-12f

// Problem constants: N=8, T=2048, D=512, K=64, M=N*T=16384
__device__ __nv_bfloat16 g_xb[16384 * 512];  // bf16 copy of x (32 MB)
__device__ __nv_bfloat16 g_ab[16384 * 64];   // a' = softmax * inv_norm, bf16 (2 MB)
__device__ float g_asum[512];                // sum_t a[n,t,k] (exact fp32)
__device__ float g_vlad[262144];             // [n][k][d] fp32 accumulation
__device__ float g_gsum[8];

// ---------------------------------------------------------------------------
__device__ __forceinline__ uint32_t smem_u32(const void* p) {
    return (uint32_t)__cvta_generic_to_shared(p);
}
__device__ __forceinline__ void ldsm_x4(uint32_t addr, uint32_t& r0, uint32_t& r1,
                                        uint32_t& r2, uint32_t& r3) {
    asm volatile("ldmatrix.sync.aligned.m8n8.x4.shared.b16 {%0,%1,%2,%3}, [%4];"
                 : "=r"(r0), "=r"(r1), "=r"(r2), "=r"(r3) : "r"(addr));
}
__device__ __forceinline__ void ldsm_x4t(uint32_t addr, uint32_t& r0, uint32_t& r1,
                                         uint32_t& r2, uint32_t& r3) {
    asm volatile("ldmatrix.sync.aligned.m8n8.x4.trans.shared.b16 {%0,%1,%2,%3}, [%4];"
                 : "=r"(r0), "=r"(r1), "=r"(r2), "=r"(r3) : "r"(addr));
}
__device__ __forceinline__ void mma16816(float c[4], uint32_t a0, uint32_t a1,
                                         uint32_t a2, uint32_t a3,
                                         uint32_t b0, uint32_t b1) {
    asm volatile(
        "mma.sync.aligned.m16n8k16.row.col.f32.bf16.bf16.f32 "
        "{%0,%1,%2,%3}, {%4,%5,%6,%7}, {%8,%9}, {%0,%1,%2,%3};"
        : "+f"(c[0]), "+f"(c[1]), "+f"(c[2]), "+f"(c[3])
        : "r"(a0), "r"(a1), "r"(a2), "r"(a3), "r"(b0), "r"(b1));
}

// ---------------------------------------------------------------------------
// K0: zero accumulators
// ---------------------------------------------------------------------------
__global__ void zero_kernel() {
    int i = blockIdx.x * 256 + threadIdx.x;
    if (i < 262144) g_vlad[i] = 0.f;
    if (i < 512)    g_asum[i] = 0.f;
    if (i < 8)      g_gsum[i] = 0.f;
}

// ---------------------------------------------------------------------------
// K1: fused  x->bf16 convert  +  row L2-norm  +  logits MMA  +  softmax
//     grid 128 (M tile = 128 rows), 256 threads (8 warps)
//     Each warp: 16 rows x 64 cols via m16n8k16 bf16 MMA.
// ---------------------------------------------------------------------------
__global__ __launch_bounds__(256) void logits_kernel(
        const float* __restrict__ x, const float* __restrict__ W,
        const float* __restrict__ bias) {
    // raw shared: mainloop tiles (xs 128x72 bf16 + ws 64x72 bf16 = 27648 B)
    // aliased by epilogue C matrix (128x65 f32 = 33280 B)
    __shared__ __align__(16) unsigned char smraw[128 * 65 * 4];
    __nv_bfloat16 (*xs)[72] = (__nv_bfloat16 (*)[72])smraw;
    __nv_bfloat16 (*ws)[72] = (__nv_bfloat16 (*)[72])(smraw + 128 * 72 * 2);
    float (*csm)[65] = (float (*)[65])smraw;

    __shared__ float rowsq[128];
    __shared__ float rowinv[128];
    __shared__ float rowrcp[128];
    __shared__ float sAsum[64];
    __shared__ float sbias[64];

    const int tid = threadIdx.x;
    const int w   = tid >> 5;
    const int l   = tid & 31;
    const int m0  = blockIdx.x * 128;

    if (tid < 64)  { sbias[tid] = bias[tid]; sAsum[tid] = 0.f; }
    if (tid < 128) rowsq[tid] = 0.f;

    float acc[8][4];
#pragma unroll
    for (int i = 0; i < 8; i++)
#pragma unroll
        for (int j = 0; j < 4; j++) acc[i][j] = 0.f;

    // ldmatrix lane address components
    const int a_row  = (l & 7) + ((l >> 3) & 1) * 8;   // A: rows m within 16
    const int a_koff = (l >> 4) * 8;                   // A: k within 16
    const int b_row  = ((l >> 4) * 8) + (l & 7);       // B: rows n within 16
    const int b_koff = ((l >> 3) & 1) * 8;             // B: k within 16
    const int m0w    = w * 16;

    for (int kb = 0; kb < 8; kb++) {
        const int koff = kb * 64;
        __syncthreads();
        // ---- load + convert x tile (128 rows x 64 cols), fp32 row-sumsq ----
#pragma unroll 4
        for (int i = 0; i < 16; i++) {
            const int r = w * 16 + i;
            const float2 v = *(const float2*)(x + (size_t)(m0 + r) * 512 + koff + 2 * l);
            float sq = v.x * v.x + v.y * v.y;
            sq += __shfl_xor_sync(~0u, sq, 16);
            sq += __shfl_xor_sync(~0u, sq, 8);
            sq += __shfl_xor_sync(~0u, sq, 4);
            sq += __shfl_xor_sync(~0u, sq, 2);
            sq += __shfl_xor_sync(~0u, sq, 1);
            if (l == 0) rowsq[r] += sq;
            __nv_bfloat162 bv = __floats2bfloat162_rn(v.x, v.y);
            *(__nv_bfloat162*)&xs[r][2 * l] = bv;
            *(__nv_bfloat162*)(g_xb + (size_t)(m0 + r) * 512 + koff + 2 * l) = bv;
        }
        // ---- load + convert W tile (64 rows x 64 cols) ----
#pragma unroll
        for (int i = 0; i < 8; i++) {
            const int r = w * 8 + i;
            const float2 v = *(const float2*)(W + (size_t)r * 512 + koff + 2 * l);
            *(__nv_bfloat162*)&ws[r][2 * l] = __floats2bfloat162_rn(v.x, v.y);
        }
        __syncthreads();
        // ---- MMA: 4 k-steps of 16 ----
#pragma unroll
        for (int ks = 0; ks < 4; ks++) {
            const int k0 = ks * 16;
            uint32_t a0, a1, a2, a3;
            ldsm_x4(smem_u32(&xs[m0w + a_row][k0 + a_koff]), a0, a1, a2, a3);
#pragma unroll
            for (int nf2 = 0; nf2 < 4; nf2++) {
                uint32_t b0, b1, b2, b3;
                ldsm_x4(smem_u32(&ws[nf2 * 16 + b_row][k0 + b_koff]), b0, b1, b2, b3);
                mma16816(acc[nf2 * 2],     a0, a1, a2, a3, b0, b1);
                mma16816(acc[nf2 * 2 + 1], a0, a1, a2, a3, b2, b3);
            }
        }
    }
    __syncthreads();   // mainloop tiles dead; csm may be written

    if (tid < 128) rowinv[tid] = 1.f / fmaxf(sqrtf(rowsq[tid]), EPSF);

    // dump accumulators to csm
    const int g  = l >> 2;
    const int c2 = (l & 3) * 2;
#pragma unroll
    for (int nf = 0; nf < 8; nf++) {
        const int col = nf * 8 + c2;
        csm[m0w + g][col]         = acc[nf][0];
        csm[m0w + g][col + 1]     = acc[nf][1];
        csm[m0w + g + 8][col]     = acc[nf][2];
        csm[m0w + g + 8][col + 1] = acc[nf][3];
    }
    __syncthreads();

    // softmax per row (one thread per row)
    if (tid < 128) {
        const int row = tid;
        const float inv = rowinv[row];
        float mx = -1e30f;
#pragma unroll 8
        for (int j = 0; j < 64; j++) {
            float t = csm[row][j] * inv + sbias[j];
            csm[row][j] = t;
            mx = fmaxf(mx, t);
        }
        float s = 0.f;
#pragma unroll 8
        for (int j = 0; j < 64; j++) {
            float e = __expf(csm[row][j] - mx);
            csm[row][j] = e;
            s += e;
        }
        rowrcp[row] = 1.f / s;
    }
    __syncthreads();

    // coalesced convert/store a' = a*inv, fp32 column sums for asum
    float cs0 = 0.f, cs1 = 0.f;
#pragma unroll 4
    for (int i = 0; i < 16; i++) {
        const int r = w * 16 + i;
        const float rcp = rowrcp[r], inv = rowinv[r];
        const float a0 = csm[r][2 * l]     * rcp;
        const float a1 = csm[r][2 * l + 1] * rcp;
        cs0 += a0; cs1 += a1;
        *(__nv_bfloat162*)(g_ab + (size_t)(m0 + r) * 64 + 2 * l) =
            __floats2bfloat162_rn(a0 * inv, a1 * inv);
    }
    atomicAdd(&sAsum[2 * l],     cs0);
    atomicAdd(&sAsum[2 * l + 1], cs1);
    __syncthreads();
    if (tid < 64) atomicAdd(&g_asum[(m0 >> 11) * 64 + tid], sAsum[tid]);
}

// ---------------------------------------------------------------------------
// K2: VLAD MMA   g_vlad[n,k,d] += sum_t a'[n,t,k] * xb[n,t,d]
//     grid (4 d-tiles x 4 t-splits x 8 n) = 128 blocks, 256 threads.
//     Block computes C[64 k][128 d] over 512 t's via bf16 MMA (trans loads).
// ---------------------------------------------------------------------------
__global__ __launch_bounds__(256) void vlad_kernel() {
    __shared__ __align__(16) __nv_bfloat16 as[64][72];    // [t][k]
    __shared__ __align__(16) __nv_bfloat16 xsb[64][136];  // [t][d]

    const int tid = threadIdx.x;
    const int w   = tid >> 5;
    const int l   = tid & 31;
    const int d0  = blockIdx.x * 128;
    const int tb  = blockIdx.y * 512;
    const int n   = blockIdx.z;

    const int wm = (w & 3) * 16;   // cluster rows
    const int wn = (w >> 2) * 64;  // d cols

    float acc[8][4];
#pragma unroll
    for (int i = 0; i < 8; i++)
#pragma unroll
        for (int j = 0; j < 4; j++) acc[i][j] = 0.f;

    // trans-ldmatrix lane address components
    const int at_row = ((l >> 4) * 8) + (l & 7);        // A: t within 16
    const int at_col = ((l >> 3) & 1) * 8;              // A: m(cluster) within 16
    const int bt_row = (((l >> 3) & 1) * 8) + (l & 7);  // B: t within 16
    const int bt_col = (l >> 4) * 8;                    // B: n(d) within 16

    const size_t abase = ((size_t)n * 2048 + tb) * 64;
    const size_t xbase = ((size_t)n * 2048 + tb) * 512 + d0;

    for (int tc = 0; tc < 8; tc++) {
        __syncthreads();
        // load a' tile [64 t][64 k] (straight bf16 copy)
        {
            const int t = tid >> 2, part = tid & 3;
            const uint4* src = (const uint4*)(g_ab + abase + (size_t)(tc * 64 + t) * 64);
            uint4 v0 = src[part], v1 = src[part + 4];
            *(uint4*)&as[t][part * 8]      = v0;
            *(uint4*)&as[t][part * 8 + 32] = v1;
        }
        // load x tile [64 t][128 d] (bf16 copy from g_xb)
#pragma unroll
        for (int i = 0; i < 8; i++) {
            const int t = w + 8 * i;
            uint2 v = *(const uint2*)(g_xb + xbase + (size_t)(tc * 64 + t) * 512 + 4 * l);
            *(uint2*)&xsb[t][4 * l] = v;
        }
        __syncthreads();
#pragma unroll
        for (int ks = 0; ks < 4; ks++) {
            const int kt = ks * 16;
            uint32_t a0, a1, a2, a3;
            ldsm_x4t(smem_u32(&as[kt + at_row][wm + at_col]), a0, a1, a2, a3);
#pragma unroll
            for (int nf2 = 0; nf2 < 4; nf2++) {
                uint32_t b0, b1, b2, b3;
                ldsm_x4t(smem_u32(&xsb[kt + bt_row][wn + nf2 * 16 + bt_col]), b0, b1, b2, b3);
                mma16816(acc[nf2 * 2],     a0, a1, a2, a3, b0, b1);
                mma16816(acc[nf2 * 2 + 1], a0, a1, a2, a3, b2, b3);
            }
        }
    }

    // accumulate into g_vlad (fp32 atomics; 4 t-splits collide)
    const int g  = l >> 2;
    const int c2 = (l & 3) * 2;
    float* vb = g_vlad + (size_t)n * 32768 + d0 + wn;
#pragma unroll
    for (int nf = 0; nf < 8; nf++) {
        const int col = nf * 8 + c2;
        atomicAdd(&vb[(size_t)(wm + g) * 512 + col],         acc[nf][0]);
        atomicAdd(&vb[(size_t)(wm + g) * 512 + col + 1],     acc[nf][1]);
        atomicAdd(&vb[(size_t)(wm + g + 8) * 512 + col],     acc[nf][2]);
        atomicAdd(&vb[(size_t)(wm + g + 8) * 512 + col + 1], acc[nf][3]);
    }
}

// ---------------------------------------------------------------------------
// K3: finalize per (n,k): v = vlad - asum*c, intra L2 normalize, write out,
//     accumulate global sum of squares per n.
// ---------------------------------------------------------------------------
__global__ __launch_bounds__(128) void finalize_kernel(
        const float* __restrict__ cent, float* __restrict__ out) {
    __shared__ float red[4];
    const int row = blockIdx.x;      // 0..511 = n*64+k
    const int k   = row & 63;
    const int n   = row >> 6;
    const int t   = threadIdx.x;

    const float s = g_asum[row];
    float4 v = ((const float4*)(g_vlad + (size_t)row * 512))[t];
    float4 c = ((const float4*)(cent   + (size_t)k   * 512))[t];
    v.x -= s * c.x; v.y -= s * c.y; v.z -= s * c.z; v.w -= s * c.w;

    float sq = v.x * v.x + v.y * v.y + v.z * v.z + v.w * v.w;
#pragma unroll
    for (int o = 16; o > 0; o >>= 1) sq += __shfl_xor_sync(0xffffffffu, sq, o);
    if ((t & 31) == 0) red[t >> 5] = sq;
    __syncthreads();
    const float tot = red[0] + red[1] + red[2] + red[3];
    const float inv = 1.f / fmaxf(sqrtf(tot), EPSF);

    float4 o4;
    o4.x = v.x * inv; o4.y = v.y * inv; o4.z = v.z * inv; o4.w = v.w * inv;
    ((float4*)(out + (size_t)row * 512))[t] = o4;

    if (t == 0) atomicAdd(&g_gsum[n], tot * inv * inv);
}

// ---------------------------------------------------------------------------
// K4: global L2 normalize per n
// ---------------------------------------------------------------------------
__global__ __launch_bounds__(128) void scale_kernel(float* __restrict__ out) {
    const int n = blockIdx.x >> 6;
    const float inv = 1.f / fmaxf(sqrtf(g_gsum[n]), EPSF);
    float4* p = (float4*)out + (size_t)blockIdx.x * 128 + threadIdx.x;
    float4 v = *p;
    v.x *= inv; v.y *= inv; v.z *= inv; v.w *= inv;
    *p = v;
}

// ---------------------------------------------------------------------------
extern "C" void kernel_launch(void* const* d_in, const int* in_sizes, int n_in,
                              void* d_out, int out_size) {
    const float* x    = (const float*)d_in[0];   // [8,2048,512]
    const float* W    = (const float*)d_in[1];   // [64,512]
    const float* b    = (const float*)d_in[2];   // [64]
    const float* cent = (const float*)d_in[3];   // [64,512]
    float* out = (float*)d_out;                  // [8, 64*512]

    zero_kernel<<<1024, 256>>>();
    logits_kernel<<<128, 256>>>(x, W, b);
    vlad_kernel<<<dim3(4, 4, 8), 256>>>();
    finalize_kernel<<<512, 128>>>(cent, out);
    scale_kernel<<<512, 128>>>(out);
}

// round 4
// speedup vs baseline: 2.5145x; 1.5861x over previous
#include <cuda_runtime.h>
#include <cuda_bf16.h>
#include <cstdint>

#define EPSF 1e-12f

// Problem constants: N=8, T=2048, D=512, K=64, M=N*T=16384
// Scratch (device globals; allocation is forbidden)
__device__ float g_asum[512];              // sum_t a[n,t,k] (exact fp32)
__device__ float g_vp[16 * 8 * 64 * 512];  // VLAD partials [tc][n][k][d] (16 MB)
__device__ float g_gsum[8];

// Shared-memory geometry (bf16 elements)
#define XS_STR 520   // 128 x 520 : x tile [row][d]   (1040 B rows, 16B-phase conflict-free)
#define WS_STR 520   // 64  x 520 : W tile [k][d]
#define AS_STR 72    // 128 x 72  : a' tile [t][k]
#define SMEM_BYTES (size_t)((128 * XS_STR + 64 * WS_STR + 128 * AS_STR) * 2)

// ---------------------------------------------------------------------------
__device__ __forceinline__ uint32_t smem_u32(const void* p) {
    return (uint32_t)__cvta_generic_to_shared(p);
}
__device__ __forceinline__ void ldsm_x4(uint32_t addr, uint32_t& r0, uint32_t& r1,
                                        uint32_t& r2, uint32_t& r3) {
    asm volatile("ldmatrix.sync.aligned.m8n8.x4.shared.b16 {%0,%1,%2,%3}, [%4];"
                 : "=r"(r0), "=r"(r1), "=r"(r2), "=r"(r3) : "r"(addr));
}
__device__ __forceinline__ void ldsm_x4t(uint32_t addr, uint32_t& r0, uint32_t& r1,
                                         uint32_t& r2, uint32_t& r3) {
    asm volatile("ldmatrix.sync.aligned.m8n8.x4.trans.shared.b16 {%0,%1,%2,%3}, [%4];"
                 : "=r"(r0), "=r"(r1), "=r"(r2), "=r"(r3) : "r"(addr));
}
__device__ __forceinline__ void mma16816(float c[4], uint32_t a0, uint32_t a1,
                                         uint32_t a2, uint32_t a3,
                                         uint32_t b0, uint32_t b1) {
    asm volatile(
        "mma.sync.aligned.m16n8k16.row.col.f32.bf16.bf16.f32 "
        "{%0,%1,%2,%3}, {%4,%5,%6,%7}, {%8,%9}, {%0,%1,%2,%3};"
        : "+f"(c[0]), "+f"(c[1]), "+f"(c[2]), "+f"(c[3])
        : "r"(a0), "r"(a1), "r"(a2), "r"(a3), "r"(b0), "r"(b1));
}

// ---------------------------------------------------------------------------
// K0: zero the small accumulators
// ---------------------------------------------------------------------------
__global__ void zero_kernel() {
    int i = threadIdx.x;
    if (i < 512) g_asum[i] = 0.f;
    if (i < 8)   g_gsum[i] = 0.f;
}

// ---------------------------------------------------------------------------
// K1: FUSED  x->bf16 (smem-resident) + row L2-norm + logits MMA + softmax
//     + VLAD MMA  (one pass over x)
// grid (16 tc, 8 n), 256 threads (8 warps). Block owns rows [n*2048+tc*128, +128).
// ---------------------------------------------------------------------------
__global__ __launch_bounds__(256) void fused_kernel(
        const float* __restrict__ x, const float* __restrict__ W,
        const float* __restrict__ bias) {
    extern __shared__ __align__(16) __nv_bfloat16 sm[];
    __nv_bfloat16 (*xs)[XS_STR] = (__nv_bfloat16 (*)[XS_STR])sm;
    __nv_bfloat16 (*ws)[WS_STR] = (__nv_bfloat16 (*)[WS_STR])(sm + 128 * XS_STR);
    __nv_bfloat16 (*as)[AS_STR] = (__nv_bfloat16 (*)[AS_STR])(sm + 128 * XS_STR + 64 * WS_STR);

    __shared__ float rowsq[128];
    __shared__ float rowinv[128];
    __shared__ float sbias[64];

    const int tid = threadIdx.x;
    const int w   = tid >> 5;
    const int l   = tid & 31;
    const int tc  = blockIdx.x;
    const int n   = blockIdx.y;
    const size_t m0 = (size_t)n * 2048 + tc * 128;

    if (tid < 64)  sbias[tid] = bias[tid];
    if (tid < 128) rowsq[tid] = 0.f;
    __syncthreads();

    // ---- Phase 1: load + convert x tile [128 x 512] and W tile [64 x 512] ----
    {
        const float4* xg = (const float4*)(x + m0 * 512);
#pragma unroll 4
        for (int it = 0; it < 64; it++) {
            const int idx = tid + it * 256;
            const int r   = idx >> 7;
            const int c4  = idx & 127;
            float4 v = xg[(size_t)r * 128 + c4];
            float sq = v.x * v.x + v.y * v.y + v.z * v.z + v.w * v.w;
            sq += __shfl_xor_sync(~0u, sq, 16);
            sq += __shfl_xor_sync(~0u, sq, 8);
            sq += __shfl_xor_sync(~0u, sq, 4);
            sq += __shfl_xor_sync(~0u, sq, 2);
            sq += __shfl_xor_sync(~0u, sq, 1);
            if (l == 0) atomicAdd(&rowsq[r], sq);
            *(__nv_bfloat162*)&xs[r][c4 * 4]     = __floats2bfloat162_rn(v.x, v.y);
            *(__nv_bfloat162*)&xs[r][c4 * 4 + 2] = __floats2bfloat162_rn(v.z, v.w);
        }
        const float4* wg = (const float4*)W;
#pragma unroll 4
        for (int it = 0; it < 32; it++) {
            const int idx = tid + it * 256;
            const int r   = idx >> 7;
            const int c4  = idx & 127;
            float4 v = wg[(size_t)r * 128 + c4];
            *(__nv_bfloat162*)&ws[r][c4 * 4]     = __floats2bfloat162_rn(v.x, v.y);
            *(__nv_bfloat162*)&ws[r][c4 * 4 + 2] = __floats2bfloat162_rn(v.z, v.w);
        }
    }
    __syncthreads();
    if (tid < 128) rowinv[tid] = 1.f / fmaxf(sqrtf(rowsq[tid]), EPSF);
    __syncthreads();

    // ---- Phase 2: logits MMA  C[128 m x 64 k] over D=512 ----
    const int m0w = w * 16;
    const int a_row  = (l & 7) + ((l >> 3) & 1) * 8;
    const int a_koff = (l >> 4) * 8;
    const int b_row  = ((l >> 4) * 8) + (l & 7);
    const int b_koff = ((l >> 3) & 1) * 8;

    float acc[8][4];
#pragma unroll
    for (int i = 0; i < 8; i++)
#pragma unroll
        for (int j = 0; j < 4; j++) acc[i][j] = 0.f;

#pragma unroll 4
    for (int ks = 0; ks < 32; ks++) {
        const int k0 = ks * 16;
        uint32_t a0, a1, a2, a3;
        ldsm_x4(smem_u32(&xs[m0w + a_row][k0 + a_koff]), a0, a1, a2, a3);
#pragma unroll
        for (int nf2 = 0; nf2 < 4; nf2++) {
            uint32_t b0, b1, b2, b3;
            ldsm_x4(smem_u32(&ws[nf2 * 16 + b_row][k0 + b_koff]), b0, b1, b2, b3);
            mma16816(acc[nf2 * 2],     a0, a1, a2, a3, b0, b1);
            mma16816(acc[nf2 * 2 + 1], a0, a1, a2, a3, b2, b3);
        }
    }

    // ---- Phase 3: register softmax (row of 64 lives in 4 lanes sharing g) ----
    {
        const int g  = l >> 2;
        const int c2 = (l & 3) * 2;
        const int r0 = m0w + g, r1 = r0 + 8;
        const float inv0 = rowinv[r0], inv1 = rowinv[r1];

        float L0[16], L1[16];
#pragma unroll
        for (int nf = 0; nf < 8; nf++) {
            const int col = nf * 8 + c2;
            L0[2 * nf]     = acc[nf][0] * inv0 + sbias[col];
            L0[2 * nf + 1] = acc[nf][1] * inv0 + sbias[col + 1];
            L1[2 * nf]     = acc[nf][2] * inv1 + sbias[col];
            L1[2 * nf + 1] = acc[nf][3] * inv1 + sbias[col + 1];
        }
        float mx0 = -1e30f, mx1 = -1e30f;
#pragma unroll
        for (int j = 0; j < 16; j++) { mx0 = fmaxf(mx0, L0[j]); mx1 = fmaxf(mx1, L1[j]); }
        mx0 = fmaxf(mx0, __shfl_xor_sync(~0u, mx0, 1));
        mx0 = fmaxf(mx0, __shfl_xor_sync(~0u, mx0, 2));
        mx1 = fmaxf(mx1, __shfl_xor_sync(~0u, mx1, 1));
        mx1 = fmaxf(mx1, __shfl_xor_sync(~0u, mx1, 2));
        float s0 = 0.f, s1 = 0.f;
#pragma unroll
        for (int j = 0; j < 16; j++) {
            L0[j] = __expf(L0[j] - mx0); s0 += L0[j];
            L1[j] = __expf(L1[j] - mx1); s1 += L1[j];
        }
        s0 += __shfl_xor_sync(~0u, s0, 1); s0 += __shfl_xor_sync(~0u, s0, 2);
        s1 += __shfl_xor_sync(~0u, s1, 1); s1 += __shfl_xor_sync(~0u, s1, 2);
        const float rcp0 = 1.f / s0, rcp1 = 1.f / s1;

        float cs[16];
#pragma unroll
        for (int j = 0; j < 16; j++) {
            L0[j] *= rcp0; L1[j] *= rcp1;          // a values (exact fp32)
            cs[j] = L0[j] + L1[j];
        }
        // column sums across the warp's 16 rows (reduce over g = lane bits 2..4)
#pragma unroll
        for (int j = 0; j < 16; j++) {
            cs[j] += __shfl_xor_sync(~0u, cs[j], 4);
            cs[j] += __shfl_xor_sync(~0u, cs[j], 8);
            cs[j] += __shfl_xor_sync(~0u, cs[j], 16);
        }
        if (l < 4) {
#pragma unroll
            for (int nf = 0; nf < 8; nf++) {
                const int col = nf * 8 + c2;
                atomicAdd(&g_asum[n * 64 + col],     cs[2 * nf]);
                atomicAdd(&g_asum[n * 64 + col + 1], cs[2 * nf + 1]);
            }
        }
        // store a' = a * inv into as[t][k]
#pragma unroll
        for (int nf = 0; nf < 8; nf++) {
            const int col = nf * 8 + c2;
            *(__nv_bfloat162*)&as[r0][col] =
                __floats2bfloat162_rn(L0[2 * nf] * inv0, L0[2 * nf + 1] * inv0);
            *(__nv_bfloat162*)&as[r1][col] =
                __floats2bfloat162_rn(L1[2 * nf] * inv1, L1[2 * nf + 1] * inv1);
        }
    }
    __syncthreads();

    // ---- Phase 4: VLAD MMA  C[64 k x 512 d] = a'^T (64x128) * xs (128x512) ----
    const int wm  = (w & 3) * 16;        // cluster rows
    const int wn2 = (w >> 2) * 64;       // d sub-column within 128-wide tile
    const int at_row = ((l >> 4) * 8) + (l & 7);
    const int at_col = ((l >> 3) & 1) * 8;
    const int bt_row = (((l >> 3) & 1) * 8) + (l & 7);
    const int bt_col = (l >> 4) * 8;

    // hoist A (a') fragments for all 8 t-steps
    uint32_t ar[8][4];
#pragma unroll
    for (int ts = 0; ts < 8; ts++)
        ldsm_x4t(smem_u32(&as[ts * 16 + at_row][wm + at_col]),
                 ar[ts][0], ar[ts][1], ar[ts][2], ar[ts][3]);

    float* vbase = g_vp + ((size_t)(tc * 8 + n) * 64) * 512;
    const int g  = l >> 2;
    const int c2 = (l & 3) * 2;

#pragma unroll
    for (int dt = 0; dt < 4; dt++) {
        const int dbase = dt * 128 + wn2;
        float vacc[8][4];
#pragma unroll
        for (int i = 0; i < 8; i++)
#pragma unroll
            for (int j = 0; j < 4; j++) vacc[i][j] = 0.f;

#pragma unroll
        for (int ts = 0; ts < 8; ts++) {
            const int kt = ts * 16;
#pragma unroll
            for (int nf2 = 0; nf2 < 4; nf2++) {
                uint32_t b0, b1, b2, b3;
                ldsm_x4t(smem_u32(&xs[kt + bt_row][dbase + nf2 * 16 + bt_col]),
                         b0, b1, b2, b3);
                mma16816(vacc[nf2 * 2],     ar[ts][0], ar[ts][1], ar[ts][2], ar[ts][3], b0, b1);
                mma16816(vacc[nf2 * 2 + 1], ar[ts][0], ar[ts][1], ar[ts][2], ar[ts][3], b2, b3);
            }
        }
        // plain (non-atomic) partial stores
#pragma unroll
        for (int nf = 0; nf < 8; nf++) {
            const int col = dbase + nf * 8 + c2;
            float2 v0 = make_float2(vacc[nf][0], vacc[nf][1]);
            float2 v1 = make_float2(vacc[nf][2], vacc[nf][3]);
            *(float2*)&vbase[(size_t)(wm + g) * 512 + col]     = v0;
            *(float2*)&vbase[(size_t)(wm + g + 8) * 512 + col] = v1;
        }
    }
}

// ---------------------------------------------------------------------------
// K2: finalize per (n,k): sum 16 partials, v -= asum*c, intra L2 norm, write,
//     accumulate per-n global sum of squares.
// ---------------------------------------------------------------------------
__global__ __launch_bounds__(128) void finalize_kernel(
        const float* __restrict__ cent, float* __restrict__ out) {
    __shared__ float red[4];
    const int row = blockIdx.x;      // n*64+k
    const int k   = row & 63;
    const int n   = row >> 6;
    const int t   = threadIdx.x;

    float4 v = make_float4(0.f, 0.f, 0.f, 0.f);
#pragma unroll
    for (int p = 0; p < 16; p++) {
        const float4 u = ((const float4*)(g_vp + ((size_t)(p * 8 + n) * 64 + k) * 512))[t];
        v.x += u.x; v.y += u.y; v.z += u.z; v.w += u.w;
    }
    const float s = g_asum[row];
    const float4 c = ((const float4*)(cent + (size_t)k * 512))[t];
    v.x -= s * c.x; v.y -= s * c.y; v.z -= s * c.z; v.w -= s * c.w;

    float sq = v.x * v.x + v.y * v.y + v.z * v.z + v.w * v.w;
#pragma unroll
    for (int o = 16; o > 0; o >>= 1) sq += __shfl_xor_sync(0xffffffffu, sq, o);
    if ((t & 31) == 0) red[t >> 5] = sq;
    __syncthreads();
    const float tot = red[0] + red[1] + red[2] + red[3];
    const float inv = 1.f / fmaxf(sqrtf(tot), EPSF);

    float4 o4;
    o4.x = v.x * inv; o4.y = v.y * inv; o4.z = v.z * inv; o4.w = v.w * inv;
    ((float4*)(out + (size_t)row * 512))[t] = o4;

    if (t == 0) atomicAdd(&g_gsum[n], tot * inv * inv);
}

// ---------------------------------------------------------------------------
// K3: global L2 normalize per n
// ---------------------------------------------------------------------------
__global__ __launch_bounds__(128) void scale_kernel(float* __restrict__ out) {
    const int n = blockIdx.x >> 6;
    const float inv = 1.f / fmaxf(sqrtf(g_gsum[n]), EPSF);
    float4* p = (float4*)out + (size_t)blockIdx.x * 128 + threadIdx.x;
    float4 v = *p;
    v.x *= inv; v.y *= inv; v.z *= inv; v.w *= inv;
    *p = v;
}

// ---------------------------------------------------------------------------
extern "C" void kernel_launch(void* const* d_in, const int* in_sizes, int n_in,
                              void* d_out, int out_size) {
    const float* x    = (const float*)d_in[0];   // [8,2048,512]
    const float* W    = (const float*)d_in[1];   // [64,512]
    const float* b    = (const float*)d_in[2];   // [64]
    const float* cent = (const float*)d_in[3];   // [64,512]
    float* out = (float*)d_out;                  // [8, 64*512]

    cudaFuncSetAttribute(fused_kernel,
                         cudaFuncAttributeMaxDynamicSharedMemorySize,
                         (int)SMEM_BYTES);

    zero_kernel<<<1, 512>>>();
    fused_kernel<<<dim3(16, 8), 256, SMEM_BYTES>>>(x, W, b);
    finalize_kernel<<<512, 128>>>(cent, out);
    scale_kernel<<<512, 128>>>(out);
}

// round 5
// speedup vs baseline: 2.8240x; 1.1231x over previous
#include <cuda_runtime.h>
#include <cuda_bf16.h>
#include <cstdint>

#define EPSF 1e-12f

// Problem constants: N=8, T=2048, D=512, K=64, M=N*T=16384
// Scratch (device globals; allocation is forbidden). No pre-zeroing needed:
// every element below is plainly overwritten by fused_kernel each call.
__device__ __nv_bfloat16 g_vpb[16 * 8 * 64 * 512];  // VLAD partials [tc][n][k][d] (8 MB)
__device__ float g_asump[16 * 8 * 64];              // asum partials [tc][n][k]

// Shared-memory geometry (bf16 elements)
#define XS_STR 520   // 128 x 520 : x tile [row][d]
#define WS_STR 520   // 64  x 520 : W tile [k][d]
#define AS_STR 72    // 128 x 72  : a' tile [t][k]
#define SMEM_BYTES (size_t)((128 * XS_STR + 64 * WS_STR + 128 * AS_STR) * 2)

// ---------------------------------------------------------------------------
__device__ __forceinline__ uint32_t smem_u32(const void* p) {
    return (uint32_t)__cvta_generic_to_shared(p);
}
__device__ __forceinline__ void ldsm_x4(uint32_t addr, uint32_t& r0, uint32_t& r1,
                                        uint32_t& r2, uint32_t& r3) {
    asm volatile("ldmatrix.sync.aligned.m8n8.x4.shared.b16 {%0,%1,%2,%3}, [%4];"
                 : "=r"(r0), "=r"(r1), "=r"(r2), "=r"(r3) : "r"(addr));
}
__device__ __forceinline__ void ldsm_x4t(uint32_t addr, uint32_t& r0, uint32_t& r1,
                                         uint32_t& r2, uint32_t& r3) {
    asm volatile("ldmatrix.sync.aligned.m8n8.x4.trans.shared.b16 {%0,%1,%2,%3}, [%4];"
                 : "=r"(r0), "=r"(r1), "=r"(r2), "=r"(r3) : "r"(addr));
}
__device__ __forceinline__ void mma16816(float c[4], uint32_t a0, uint32_t a1,
                                         uint32_t a2, uint32_t a3,
                                         uint32_t b0, uint32_t b1) {
    asm volatile(
        "mma.sync.aligned.m16n8k16.row.col.f32.bf16.bf16.f32 "
        "{%0,%1,%2,%3}, {%4,%5,%6,%7}, {%8,%9}, {%0,%1,%2,%3};"
        : "+f"(c[0]), "+f"(c[1]), "+f"(c[2]), "+f"(c[3])
        : "r"(a0), "r"(a1), "r"(a2), "r"(a3), "r"(b0), "r"(b1));
}

// ---------------------------------------------------------------------------
// K1: FUSED  x->bf16 (smem-resident) + row L2-norm + logits MMA + softmax
//     + VLAD MMA  (one pass over x)
// grid (16 tc, 8 n), 256 threads (8 warps). Block owns rows [n*2048+tc*128, +128).
// ---------------------------------------------------------------------------
__global__ __launch_bounds__(256) void fused_kernel(
        const float* __restrict__ x, const float* __restrict__ W,
        const float* __restrict__ bias) {
    extern __shared__ __align__(16) __nv_bfloat16 sm[];
    __nv_bfloat16 (*xs)[XS_STR] = (__nv_bfloat16 (*)[XS_STR])sm;
    __nv_bfloat16 (*ws)[WS_STR] = (__nv_bfloat16 (*)[WS_STR])(sm + 128 * XS_STR);
    __nv_bfloat16 (*as)[AS_STR] = (__nv_bfloat16 (*)[AS_STR])(sm + 128 * XS_STR + 64 * WS_STR);

    __shared__ float rowsq[128];
    __shared__ float rowinv[128];
    __shared__ float sbias[64];
    __shared__ float sAsum[64];

    const int tid = threadIdx.x;
    const int w   = tid >> 5;
    const int l   = tid & 31;
    const int tc  = blockIdx.x;
    const int n   = blockIdx.y;
    const size_t m0 = (size_t)n * 2048 + tc * 128;

    if (tid < 64)  { sbias[tid] = bias[tid]; sAsum[tid] = 0.f; }
    if (tid < 128) rowsq[tid] = 0.f;
    __syncthreads();

    // ---- Phase 1: load + convert x tile [128 x 512] and W tile [64 x 512] ----
    {
        const float4* xg = (const float4*)(x + m0 * 512);
#pragma unroll 4
        for (int it = 0; it < 64; it++) {
            const int idx = tid + it * 256;
            const int r   = idx >> 7;
            const int c4  = idx & 127;
            float4 v = xg[(size_t)r * 128 + c4];
            float sq = v.x * v.x + v.y * v.y + v.z * v.z + v.w * v.w;
            sq += __shfl_xor_sync(~0u, sq, 16);
            sq += __shfl_xor_sync(~0u, sq, 8);
            sq += __shfl_xor_sync(~0u, sq, 4);
            sq += __shfl_xor_sync(~0u, sq, 2);
            sq += __shfl_xor_sync(~0u, sq, 1);
            if (l == 0) atomicAdd(&rowsq[r], sq);
            *(__nv_bfloat162*)&xs[r][c4 * 4]     = __floats2bfloat162_rn(v.x, v.y);
            *(__nv_bfloat162*)&xs[r][c4 * 4 + 2] = __floats2bfloat162_rn(v.z, v.w);
        }
        const float4* wg = (const float4*)W;
#pragma unroll 4
        for (int it = 0; it < 32; it++) {
            const int idx = tid + it * 256;
            const int r   = idx >> 7;
            const int c4  = idx & 127;
            float4 v = wg[(size_t)r * 128 + c4];
            *(__nv_bfloat162*)&ws[r][c4 * 4]     = __floats2bfloat162_rn(v.x, v.y);
            *(__nv_bfloat162*)&ws[r][c4 * 4 + 2] = __floats2bfloat162_rn(v.z, v.w);
        }
    }
    __syncthreads();
    if (tid < 128) rowinv[tid] = 1.f / fmaxf(sqrtf(rowsq[tid]), EPSF);
    __syncthreads();

    // ---- Phase 2: logits MMA  C[128 m x 64 k] over D=512 ----
    const int m0w = w * 16;
    const int a_row  = (l & 7) + ((l >> 3) & 1) * 8;
    const int a_koff = (l >> 4) * 8;
    const int b_row  = ((l >> 4) * 8) + (l & 7);
    const int b_koff = ((l >> 3) & 1) * 8;

    float acc[8][4];
#pragma unroll
    for (int i = 0; i < 8; i++)
#pragma unroll
        for (int j = 0; j < 4; j++) acc[i][j] = 0.f;

#pragma unroll 4
    for (int ks = 0; ks < 32; ks++) {
        const int k0 = ks * 16;
        uint32_t a0, a1, a2, a3;
        ldsm_x4(smem_u32(&xs[m0w + a_row][k0 + a_koff]), a0, a1, a2, a3);
#pragma unroll
        for (int nf2 = 0; nf2 < 4; nf2++) {
            uint32_t b0, b1, b2, b3;
            ldsm_x4(smem_u32(&ws[nf2 * 16 + b_row][k0 + b_koff]), b0, b1, b2, b3);
            mma16816(acc[nf2 * 2],     a0, a1, a2, a3, b0, b1);
            mma16816(acc[nf2 * 2 + 1], a0, a1, a2, a3, b2, b3);
        }
    }

    // ---- Phase 3: register softmax (row of 64 lives in 4 lanes sharing g) ----
    {
        const int g  = l >> 2;
        const int c2 = (l & 3) * 2;
        const int r0 = m0w + g, r1 = r0 + 8;
        const float inv0 = rowinv[r0], inv1 = rowinv[r1];

        float L0[16], L1[16];
#pragma unroll
        for (int nf = 0; nf < 8; nf++) {
            const int col = nf * 8 + c2;
            L0[2 * nf]     = acc[nf][0] * inv0 + sbias[col];
            L0[2 * nf + 1] = acc[nf][1] * inv0 + sbias[col + 1];
            L1[2 * nf]     = acc[nf][2] * inv1 + sbias[col];
            L1[2 * nf + 1] = acc[nf][3] * inv1 + sbias[col + 1];
        }
        float mx0 = -1e30f, mx1 = -1e30f;
#pragma unroll
        for (int j = 0; j < 16; j++) { mx0 = fmaxf(mx0, L0[j]); mx1 = fmaxf(mx1, L1[j]); }
        mx0 = fmaxf(mx0, __shfl_xor_sync(~0u, mx0, 1));
        mx0 = fmaxf(mx0, __shfl_xor_sync(~0u, mx0, 2));
        mx1 = fmaxf(mx1, __shfl_xor_sync(~0u, mx1, 1));
        mx1 = fmaxf(mx1, __shfl_xor_sync(~0u, mx1, 2));
        float s0 = 0.f, s1 = 0.f;
#pragma unroll
        for (int j = 0; j < 16; j++) {
            L0[j] = __expf(L0[j] - mx0); s0 += L0[j];
            L1[j] = __expf(L1[j] - mx1); s1 += L1[j];
        }
        s0 += __shfl_xor_sync(~0u, s0, 1); s0 += __shfl_xor_sync(~0u, s0, 2);
        s1 += __shfl_xor_sync(~0u, s1, 1); s1 += __shfl_xor_sync(~0u, s1, 2);
        const float rcp0 = 1.f / s0, rcp1 = 1.f / s1;

        float cs[16];
#pragma unroll
        for (int j = 0; j < 16; j++) {
            L0[j] *= rcp0; L1[j] *= rcp1;          // a values (exact fp32)
            cs[j] = L0[j] + L1[j];
        }
        // column sums across the warp's 16 rows (reduce over g = lane bits 2..4)
#pragma unroll
        for (int j = 0; j < 16; j++) {
            cs[j] += __shfl_xor_sync(~0u, cs[j], 4);
            cs[j] += __shfl_xor_sync(~0u, cs[j], 8);
            cs[j] += __shfl_xor_sync(~0u, cs[j], 16);
        }
        if (l < 4) {
#pragma unroll
            for (int nf = 0; nf < 8; nf++) {
                const int col = nf * 8 + c2;
                atomicAdd(&sAsum[col],     cs[2 * nf]);        // smem atomics only
                atomicAdd(&sAsum[col + 1], cs[2 * nf + 1]);
            }
        }
        // store a' = a * inv into as[t][k]
#pragma unroll
        for (int nf = 0; nf < 8; nf++) {
            const int col = nf * 8 + c2;
            *(__nv_bfloat162*)&as[r0][col] =
                __floats2bfloat162_rn(L0[2 * nf] * inv0, L0[2 * nf + 1] * inv0);
            *(__nv_bfloat162*)&as[r1][col] =
                __floats2bfloat162_rn(L1[2 * nf] * inv1, L1[2 * nf + 1] * inv1);
        }
    }
    __syncthreads();
    if (tid < 64)  // plain (non-atomic) asum partial store -> no pre-zero needed
        g_asump[(tc * 8 + n) * 64 + tid] = sAsum[tid];

    // ---- Phase 4: VLAD MMA  C[64 k x 512 d] = a'^T (64x128) * xs (128x512) ----
    const int wm  = (w & 3) * 16;        // cluster rows
    const int wn2 = (w >> 2) * 64;       // d sub-column within 128-wide tile
    const int at_row = ((l >> 4) * 8) + (l & 7);
    const int at_col = ((l >> 3) & 1) * 8;
    const int bt_row = (((l >> 3) & 1) * 8) + (l & 7);
    const int bt_col = (l >> 4) * 8;

    uint32_t ar[8][4];
#pragma unroll
    for (int ts = 0; ts < 8; ts++)
        ldsm_x4t(smem_u32(&as[ts * 16 + at_row][wm + at_col]),
                 ar[ts][0], ar[ts][1], ar[ts][2], ar[ts][3]);

    __nv_bfloat16* vbase = g_vpb + ((size_t)(tc * 8 + n) * 64) * 512;
    const int g  = l >> 2;
    const int c2 = (l & 3) * 2;

#pragma unroll
    for (int dt = 0; dt < 4; dt++) {
        const int dbase = dt * 128 + wn2;
        float vacc[8][4];
#pragma unroll
        for (int i = 0; i < 8; i++)
#pragma unroll
            for (int j = 0; j < 4; j++) vacc[i][j] = 0.f;

#pragma unroll
        for (int ts = 0; ts < 8; ts++) {
            const int kt = ts * 16;
#pragma unroll
            for (int nf2 = 0; nf2 < 4; nf2++) {
                uint32_t b0, b1, b2, b3;
                ldsm_x4t(smem_u32(&xs[kt + bt_row][dbase + nf2 * 16 + bt_col]),
                         b0, b1, b2, b3);
                mma16816(vacc[nf2 * 2],     ar[ts][0], ar[ts][1], ar[ts][2], ar[ts][3], b0, b1);
                mma16816(vacc[nf2 * 2 + 1], ar[ts][0], ar[ts][1], ar[ts][2], ar[ts][3], b2, b3);
            }
        }
        // plain bf16 partial stores (halved traffic vs fp32)
#pragma unroll
        for (int nf = 0; nf < 8; nf++) {
            const int col = dbase + nf * 8 + c2;
            *(__nv_bfloat162*)&vbase[(size_t)(wm + g) * 512 + col] =
                __floats2bfloat162_rn(vacc[nf][0], vacc[nf][1]);
            *(__nv_bfloat162*)&vbase[(size_t)(wm + g + 8) * 512 + col] =
                __floats2bfloat162_rn(vacc[nf][2], vacc[nf][3]);
        }
    }
}

// ---------------------------------------------------------------------------
// K2: finalize per (n,k): sum 16 bf16 partials + 16 asum partials,
//     v -= asum*c, intra L2 normalize, apply analytic global scale 1/8, write.
//     (After intra-normalization all 64 cluster vectors have unit norm, so the
//      global L2 norm is exactly sqrt(64)=8 up to fp rounding ~1e-7.)
// ---------------------------------------------------------------------------
__global__ __launch_bounds__(128) void finalize_kernel(
        const float* __restrict__ cent, float* __restrict__ out) {
    __shared__ float red[4];
    const int row = blockIdx.x;      // n*64+k
    const int k   = row & 63;
    const int n   = row >> 6;
    const int t   = threadIdx.x;     // 128 threads x 4 d = 512

    float4 v = make_float4(0.f, 0.f, 0.f, 0.f);
    float s = 0.f;
#pragma unroll
    for (int p = 0; p < 16; p++) {
        const __nv_bfloat162* vp =
            (const __nv_bfloat162*)(g_vpb + ((size_t)(p * 8 + n) * 64 + k) * 512) + t * 2;
        const float2 f0 = __bfloat1622float2(vp[0]);
        const float2 f1 = __bfloat1622float2(vp[1]);
        v.x += f0.x; v.y += f0.y; v.z += f1.x; v.w += f1.y;
        s += g_asump[(p * 8 + n) * 64 + k];
    }
    const float4 c = ((const float4*)(cent + (size_t)k * 512))[t];
    v.x -= s * c.x; v.y -= s * c.y; v.z -= s * c.z; v.w -= s * c.w;

    float sq = v.x * v.x + v.y * v.y + v.z * v.z + v.w * v.w;
#pragma unroll
    for (int o = 16; o > 0; o >>= 1) sq += __shfl_xor_sync(0xffffffffu, sq, o);
    if ((t & 31) == 0) red[t >> 5] = sq;
    __syncthreads();
    const float tot = red[0] + red[1] + red[2] + red[3];
    const float inv = 0.125f / fmaxf(sqrtf(tot), EPSF);   // intra-norm * global 1/8

    float4 o4;
    o4.x = v.x * inv; o4.y = v.y * inv; o4.z = v.z * inv; o4.w = v.w * inv;
    ((float4*)(out + (size_t)row * 512))[t] = o4;
}

// ---------------------------------------------------------------------------
extern "C" void kernel_launch(void* const* d_in, const int* in_sizes, int n_in,
                              void* d_out, int out_size) {
    const float* x    = (const float*)d_in[0];   // [8,2048,512]
    const float* W    = (const float*)d_in[1];   // [64,512]
    const float* b    = (const float*)d_in[2];   // [64]
    const float* cent = (const float*)d_in[3];   // [64,512]
    float* out = (float*)d_out;                  // [8, 64*512]

    cudaFuncSetAttribute(fused_kernel,
                         cudaFuncAttributeMaxDynamicSharedMemorySize,
                         (int)SMEM_BYTES);

    fused_kernel<<<dim3(16, 8), 256, SMEM_BYTES>>>(x, W, b);
    finalize_kernel<<<512, 128>>>(cent, out);
}

// round 6
// speedup vs baseline: 3.4787x; 1.2318x over previous
#include <cuda_runtime.h>
#include <cuda_bf16.h>
#include <cstdint>

#define EPSF 1e-12f

// Problem constants: N=8, T=2048, D=512, K=64, M=N*T=16384
// Scratch (device globals; allocation is forbidden). No pre-zeroing needed:
// every element below is plainly overwritten by fused_kernel each call.
__device__ __nv_bfloat16 g_vpb[8 * 64 * 16 * 512];  // VLAD partials [n][k][p][d] (8 MB)
__device__ float g_asump[16 * 8 * 64];              // asum partials [tc][n][k]

// Shared-memory geometry (bf16 elements)
#define XS_STR 520   // 128 x 520 : x tile [row][d]
#define WS_STR 520   // 64  x 520 : W tile [k][d]
#define AS_STR 72    // 128 x 72  : a' tile [t][k]
#define SMEM_BYTES (size_t)((128 * XS_STR + 64 * WS_STR + 128 * AS_STR) * 2)

// ---------------------------------------------------------------------------
__device__ __forceinline__ uint32_t smem_u32(const void* p) {
    return (uint32_t)__cvta_generic_to_shared(p);
}
__device__ __forceinline__ void ldsm_x4(uint32_t addr, uint32_t& r0, uint32_t& r1,
                                        uint32_t& r2, uint32_t& r3) {
    asm volatile("ldmatrix.sync.aligned.m8n8.x4.shared.b16 {%0,%1,%2,%3}, [%4];"
                 : "=r"(r0), "=r"(r1), "=r"(r2), "=r"(r3) : "r"(addr));
}
__device__ __forceinline__ void ldsm_x4t(uint32_t addr, uint32_t& r0, uint32_t& r1,
                                         uint32_t& r2, uint32_t& r3) {
    asm volatile("ldmatrix.sync.aligned.m8n8.x4.trans.shared.b16 {%0,%1,%2,%3}, [%4];"
                 : "=r"(r0), "=r"(r1), "=r"(r2), "=r"(r3) : "r"(addr));
}
__device__ __forceinline__ void mma16816(float c[4], uint32_t a0, uint32_t a1,
                                         uint32_t a2, uint32_t a3,
                                         uint32_t b0, uint32_t b1) {
    asm volatile(
        "mma.sync.aligned.m16n8k16.row.col.f32.bf16.bf16.f32 "
        "{%0,%1,%2,%3}, {%4,%5,%6,%7}, {%8,%9}, {%0,%1,%2,%3};"
        : "+f"(c[0]), "+f"(c[1]), "+f"(c[2]), "+f"(c[3])
        : "r"(a0), "r"(a1), "r"(a2), "r"(a3), "r"(b0), "r"(b1));
}

// ---------------------------------------------------------------------------
// K1: FUSED  x->bf16 (smem-resident) + row L2-norm + logits MMA + softmax
//     + VLAD MMA  (one pass over x)
// grid (16 tc, 8 n), 256 threads (8 warps). Block owns rows [n*2048+tc*128, +128).
// ---------------------------------------------------------------------------
__global__ __launch_bounds__(256) void fused_kernel(
        const float* __restrict__ x, const float* __restrict__ W,
        const float* __restrict__ bias) {
    extern __shared__ __align__(16) __nv_bfloat16 sm[];
    __nv_bfloat16 (*xs)[XS_STR] = (__nv_bfloat16 (*)[XS_STR])sm;
    __nv_bfloat16 (*ws)[WS_STR] = (__nv_bfloat16 (*)[WS_STR])(sm + 128 * XS_STR);
    __nv_bfloat16 (*as)[AS_STR] = (__nv_bfloat16 (*)[AS_STR])(sm + 128 * XS_STR + 64 * WS_STR);

    __shared__ float rowinv[128];
    __shared__ float sbias[64];
    __shared__ float sAsum[64];

    const int tid = threadIdx.x;
    const int w   = tid >> 5;
    const int l   = tid & 31;
    const int tc  = blockIdx.x;
    const int n   = blockIdx.y;
    const size_t m0 = (size_t)n * 2048 + tc * 128;

    if (tid < 64) { sbias[tid] = bias[tid]; sAsum[tid] = 0.f; }

    // ---- Phase 1: load + convert (warp-per-16-rows, fully coalesced) ----
    {
        const float4* xg = (const float4*)(x + m0 * 512);
#pragma unroll 2
        for (int rr = 0; rr < 16; rr++) {
            const int r = w * 16 + rr;
            float4 v[4];
#pragma unroll
            for (int cb = 0; cb < 4; cb++)
                v[cb] = xg[(size_t)r * 128 + cb * 32 + l];
            float sq = 0.f;
#pragma unroll
            for (int cb = 0; cb < 4; cb++) {
                sq += v[cb].x * v[cb].x + v[cb].y * v[cb].y
                    + v[cb].z * v[cb].z + v[cb].w * v[cb].w;
                const int c = (cb * 32 + l) * 4;
                *(__nv_bfloat162*)&xs[r][c]     = __floats2bfloat162_rn(v[cb].x, v[cb].y);
                *(__nv_bfloat162*)&xs[r][c + 2] = __floats2bfloat162_rn(v[cb].z, v[cb].w);
            }
            sq += __shfl_xor_sync(~0u, sq, 16);
            sq += __shfl_xor_sync(~0u, sq, 8);
            sq += __shfl_xor_sync(~0u, sq, 4);
            sq += __shfl_xor_sync(~0u, sq, 2);
            sq += __shfl_xor_sync(~0u, sq, 1);
            if (l == 0) rowinv[r] = 1.f / fmaxf(sqrtf(sq), EPSF);
        }
        const float4* wg = (const float4*)W;
#pragma unroll 2
        for (int rr = 0; rr < 8; rr++) {
            const int r = w * 8 + rr;
            float4 v[4];
#pragma unroll
            for (int cb = 0; cb < 4; cb++)
                v[cb] = wg[(size_t)r * 128 + cb * 32 + l];
#pragma unroll
            for (int cb = 0; cb < 4; cb++) {
                const int c = (cb * 32 + l) * 4;
                *(__nv_bfloat162*)&ws[r][c]     = __floats2bfloat162_rn(v[cb].x, v[cb].y);
                *(__nv_bfloat162*)&ws[r][c + 2] = __floats2bfloat162_rn(v[cb].z, v[cb].w);
            }
        }
    }
    __syncthreads();

    // ---- Phase 2: logits MMA  C[128 m x 64 k] over D=512 ----
    const int m0w = w * 16;
    const int a_row  = (l & 7) + ((l >> 3) & 1) * 8;
    const int a_koff = (l >> 4) * 8;
    const int b_row  = ((l >> 4) * 8) + (l & 7);
    const int b_koff = ((l >> 3) & 1) * 8;

    float acc[8][4];
#pragma unroll
    for (int i = 0; i < 8; i++)
#pragma unroll
        for (int j = 0; j < 4; j++) acc[i][j] = 0.f;

#pragma unroll 4
    for (int ks = 0; ks < 32; ks++) {
        const int k0 = ks * 16;
        uint32_t a0, a1, a2, a3;
        ldsm_x4(smem_u32(&xs[m0w + a_row][k0 + a_koff]), a0, a1, a2, a3);
#pragma unroll
        for (int nf2 = 0; nf2 < 4; nf2++) {
            uint32_t b0, b1, b2, b3;
            ldsm_x4(smem_u32(&ws[nf2 * 16 + b_row][k0 + b_koff]), b0, b1, b2, b3);
            mma16816(acc[nf2 * 2],     a0, a1, a2, a3, b0, b1);
            mma16816(acc[nf2 * 2 + 1], a0, a1, a2, a3, b2, b3);
        }
    }

    // ---- Phase 3: register softmax (row of 64 lives in 4 lanes sharing g) ----
    {
        const int g  = l >> 2;
        const int c2 = (l & 3) * 2;
        const int r0 = m0w + g, r1 = r0 + 8;
        const float inv0 = rowinv[r0], inv1 = rowinv[r1];

        float L0[16], L1[16];
#pragma unroll
        for (int nf = 0; nf < 8; nf++) {
            const int col = nf * 8 + c2;
            L0[2 * nf]     = acc[nf][0] * inv0 + sbias[col];
            L0[2 * nf + 1] = acc[nf][1] * inv0 + sbias[col + 1];
            L1[2 * nf]     = acc[nf][2] * inv1 + sbias[col];
            L1[2 * nf + 1] = acc[nf][3] * inv1 + sbias[col + 1];
        }
        float mx0 = -1e30f, mx1 = -1e30f;
#pragma unroll
        for (int j = 0; j < 16; j++) { mx0 = fmaxf(mx0, L0[j]); mx1 = fmaxf(mx1, L1[j]); }
        mx0 = fmaxf(mx0, __shfl_xor_sync(~0u, mx0, 1));
        mx0 = fmaxf(mx0, __shfl_xor_sync(~0u, mx0, 2));
        mx1 = fmaxf(mx1, __shfl_xor_sync(~0u, mx1, 1));
        mx1 = fmaxf(mx1, __shfl_xor_sync(~0u, mx1, 2));
        float s0 = 0.f, s1 = 0.f;
#pragma unroll
        for (int j = 0; j < 16; j++) {
            L0[j] = __expf(L0[j] - mx0); s0 += L0[j];
            L1[j] = __expf(L1[j] - mx1); s1 += L1[j];
        }
        s0 += __shfl_xor_sync(~0u, s0, 1); s0 += __shfl_xor_sync(~0u, s0, 2);
        s1 += __shfl_xor_sync(~0u, s1, 1); s1 += __shfl_xor_sync(~0u, s1, 2);
        const float rcp0 = 1.f / s0, rcp1 = 1.f / s1;

        float cs[16];
#pragma unroll
        for (int j = 0; j < 16; j++) {
            L0[j] *= rcp0; L1[j] *= rcp1;          // a values (exact fp32)
            cs[j] = L0[j] + L1[j];
        }
#pragma unroll
        for (int j = 0; j < 16; j++) {
            cs[j] += __shfl_xor_sync(~0u, cs[j], 4);
            cs[j] += __shfl_xor_sync(~0u, cs[j], 8);
            cs[j] += __shfl_xor_sync(~0u, cs[j], 16);
        }
        if (l < 4) {
#pragma unroll
            for (int nf = 0; nf < 8; nf++) {
                const int col = nf * 8 + c2;
                atomicAdd(&sAsum[col],     cs[2 * nf]);        // smem atomics only
                atomicAdd(&sAsum[col + 1], cs[2 * nf + 1]);
            }
        }
#pragma unroll
        for (int nf = 0; nf < 8; nf++) {
            const int col = nf * 8 + c2;
            *(__nv_bfloat162*)&as[r0][col] =
                __floats2bfloat162_rn(L0[2 * nf] * inv0, L0[2 * nf + 1] * inv0);
            *(__nv_bfloat162*)&as[r1][col] =
                __floats2bfloat162_rn(L1[2 * nf] * inv1, L1[2 * nf + 1] * inv1);
        }
    }
    __syncthreads();
    if (tid < 64)  // plain (non-atomic) asum partial store
        g_asump[(tc * 8 + n) * 64 + tid] = sAsum[tid];

    // ---- Phase 4: VLAD MMA  C[64 k x 512 d] = a'^T (64x128) * xs (128x512) ----
    const int wm  = (w & 3) * 16;        // cluster rows
    const int wn2 = (w >> 2) * 64;       // d sub-column within 128-wide tile
    const int at_row = ((l >> 4) * 8) + (l & 7);
    const int at_col = ((l >> 3) & 1) * 8;
    const int bt_row = (((l >> 3) & 1) * 8) + (l & 7);
    const int bt_col = (l >> 4) * 8;

    uint32_t ar[8][4];
#pragma unroll
    for (int ts = 0; ts < 8; ts++)
        ldsm_x4t(smem_u32(&as[ts * 16 + at_row][wm + at_col]),
                 ar[ts][0], ar[ts][1], ar[ts][2], ar[ts][3]);

    const int g  = l >> 2;
    const int c2 = (l & 3) * 2;
    const size_t kn0 = (size_t)n * 64;

#pragma unroll
    for (int dt = 0; dt < 4; dt++) {
        const int dbase = dt * 128 + wn2;
        float vacc[8][4];
#pragma unroll
        for (int i = 0; i < 8; i++)
#pragma unroll
            for (int j = 0; j < 4; j++) vacc[i][j] = 0.f;

#pragma unroll
        for (int ts = 0; ts < 8; ts++) {
            const int kt = ts * 16;
#pragma unroll
            for (int nf2 = 0; nf2 < 4; nf2++) {
                uint32_t b0, b1, b2, b3;
                ldsm_x4t(smem_u32(&xs[kt + bt_row][dbase + nf2 * 16 + bt_col]),
                         b0, b1, b2, b3);
                mma16816(vacc[nf2 * 2],     ar[ts][0], ar[ts][1], ar[ts][2], ar[ts][3], b0, b1);
                mma16816(vacc[nf2 * 2 + 1], ar[ts][0], ar[ts][1], ar[ts][2], ar[ts][3], b2, b3);
            }
        }
        // bf16 partial stores, layout [n][k][p=tc][d] -> finalize reads contiguous
#pragma unroll
        for (int nf = 0; nf < 8; nf++) {
            const int col = dbase + nf * 8 + c2;
            *(__nv_bfloat162*)&g_vpb[(((kn0 + wm + g) * 16 + tc) << 9) + col] =
                __floats2bfloat162_rn(vacc[nf][0], vacc[nf][1]);
            *(__nv_bfloat162*)&g_vpb[(((kn0 + wm + g + 8) * 16 + tc) << 9) + col] =
                __floats2bfloat162_rn(vacc[nf][2], vacc[nf][3]);
        }
    }
}

// ---------------------------------------------------------------------------
// K2: finalize per (n,k): 512 threads, 4 p-groups of 4 partials each,
//     smem combine, v -= asum*c, intra L2 normalize, analytic global 1/8.
// ---------------------------------------------------------------------------
__global__ __launch_bounds__(512) void finalize_kernel(
        const float* __restrict__ cent, float* __restrict__ out) {
    __shared__ float ps[3][512];
    __shared__ float red[4];
    __shared__ float s_sh;

    const int row = blockIdx.x;      // n*64+k
    const int k   = row & 63;
    const int n   = row >> 6;
    const int tid = threadIdx.x;
    const int tg  = tid >> 7;        // 0..3 (p-group)
    const int t   = tid & 127;       // d/4 index

    // asum reduce (16 partials) on warp 0
    if (tid < 32) {
        float a = (tid < 16) ? g_asump[(tid * 8 + n) * 64 + k] : 0.f;
        a += __shfl_xor_sync(~0u, a, 8);
        a += __shfl_xor_sync(~0u, a, 4);
        a += __shfl_xor_sync(~0u, a, 2);
        a += __shfl_xor_sync(~0u, a, 1);
        if (tid == 0) s_sh = a;
    }

    // each group sums 4 of the 16 contiguous partial slices
    float4 v = make_float4(0.f, 0.f, 0.f, 0.f);
    const __nv_bfloat162* base = (const __nv_bfloat162*)(g_vpb + ((size_t)row * 16) * 512);
#pragma unroll
    for (int pp = 0; pp < 4; pp++) {
        const __nv_bfloat162* vp = base + (tg * 4 + pp) * 256 + t * 2;
        const float2 f0 = __bfloat1622float2(vp[0]);
        const float2 f1 = __bfloat1622float2(vp[1]);
        v.x += f0.x; v.y += f0.y; v.z += f1.x; v.w += f1.y;
    }
    if (tg) *(float4*)&ps[tg - 1][t * 4] = v;
    __syncthreads();

    float4 ov; float tot = 0.f;
    if (tg == 0) {
        const float4 p1 = *(const float4*)&ps[0][t * 4];
        const float4 p2 = *(const float4*)&ps[1][t * 4];
        const float4 p3 = *(const float4*)&ps[2][t * 4];
        v.x += p1.x + p2.x + p3.x; v.y += p1.y + p2.y + p3.y;
        v.z += p1.z + p2.z + p3.z; v.w += p1.w + p2.w + p3.w;
        const float s = s_sh;
        const float4 c = ((const float4*)(cent + (size_t)k * 512))[t];
        v.x -= s * c.x; v.y -= s * c.y; v.z -= s * c.z; v.w -= s * c.w;
        ov = v;
        float sq = v.x * v.x + v.y * v.y + v.z * v.z + v.w * v.w;
#pragma unroll
        for (int o = 16; o > 0; o >>= 1) sq += __shfl_xor_sync(0xffffffffu, sq, o);
        if ((t & 31) == 0) red[t >> 5] = sq;
    }
    __syncthreads();
    if (tg == 0) {
        tot = red[0] + red[1] + red[2] + red[3];
        const float inv = 0.125f / fmaxf(sqrtf(tot), EPSF);  // intra-norm * global 1/8
        float4 o4;
        o4.x = ov.x * inv; o4.y = ov.y * inv; o4.z = ov.z * inv; o4.w = ov.w * inv;
        ((float4*)(out + (size_t)row * 512))[t] = o4;
    }
}

// ---------------------------------------------------------------------------
extern "C" void kernel_launch(void* const* d_in, const int* in_sizes, int n_in,
                              void* d_out, int out_size) {
    const float* x    = (const float*)d_in[0];   // [8,2048,512]
    const float* W    = (const float*)d_in[1];   // [64,512]
    const float* b    = (const float*)d_in[2];   // [64]
    const float* cent = (const float*)d_in[3];   // [64,512]
    float* out = (float*)d_out;                  // [8, 64*512]

    cudaFuncSetAttribute(fused_kernel,
                         cudaFuncAttributeMaxDynamicSharedMemorySize,
                         (int)SMEM_BYTES);

    fused_kernel<<<dim3(16, 8), 256, SMEM_BYTES>>>(x, W, b);
    finalize_kernel<<<512, 512>>>(cent, out);
}

// round 7
// speedup vs baseline: 3.5408x; 1.0179x over previous
#include <cuda_runtime.h>
#include <cuda_bf16.h>
#include <cstdint>

#define EPSF 1e-12f

// Problem constants: N=8, T=2048, D=512, K=64, M=N*T=16384
// Scratch (device globals; allocation is forbidden). No pre-zeroing needed:
// every element below is plainly overwritten by fused_kernel each call.
__device__ __nv_bfloat16 g_vpb[8 * 64 * 16 * 512];  // VLAD partials [n][k][p][d] (8 MB)
__device__ float g_asump[16 * 8 * 64];              // asum partials [tc][n][k]

// Shared-memory geometry (bf16 elements)
#define XS_STR 520   // 128 x 520 : x tile [row][d]
#define WS_STR 520   // 64  x 520 : W tile [k][d]
#define AS_STR 72    // 128 x 72  : a' tile [t][k]
#define SMEM_BYTES (size_t)((128 * XS_STR + 64 * WS_STR + 128 * AS_STR) * 2)

// ---------------------------------------------------------------------------
__device__ __forceinline__ uint32_t smem_u32(const void* p) {
    return (uint32_t)__cvta_generic_to_shared(p);
}
__device__ __forceinline__ void ldsm_x4(uint32_t addr, uint32_t& r0, uint32_t& r1,
                                        uint32_t& r2, uint32_t& r3) {
    asm volatile("ldmatrix.sync.aligned.m8n8.x4.shared.b16 {%0,%1,%2,%3}, [%4];"
                 : "=r"(r0), "=r"(r1), "=r"(r2), "=r"(r3) : "r"(addr));
}
__device__ __forceinline__ void ldsm_x4t(uint32_t addr, uint32_t& r0, uint32_t& r1,
                                         uint32_t& r2, uint32_t& r3) {
    asm volatile("ldmatrix.sync.aligned.m8n8.x4.trans.shared.b16 {%0,%1,%2,%3}, [%4];"
                 : "=r"(r0), "=r"(r1), "=r"(r2), "=r"(r3) : "r"(addr));
}
__device__ __forceinline__ void mma16816(float c[4], uint32_t a0, uint32_t a1,
                                         uint32_t a2, uint32_t a3,
                                         uint32_t b0, uint32_t b1) {
    asm volatile(
        "mma.sync.aligned.m16n8k16.row.col.f32.bf16.bf16.f32 "
        "{%0,%1,%2,%3}, {%4,%5,%6,%7}, {%8,%9}, {%0,%1,%2,%3};"
        : "+f"(c[0]), "+f"(c[1]), "+f"(c[2]), "+f"(c[3])
        : "r"(a0), "r"(a1), "r"(a2), "r"(a3), "r"(b0), "r"(b1));
}
__device__ __forceinline__ __nv_bfloat162 u2bf2(uint32_t u) {
    __nv_bfloat162 r; *(uint32_t*)&r = u; return r;
}
__device__ __forceinline__ uint32_t bf22u(__nv_bfloat162 v) {
    return *(uint32_t*)&v;
}
__device__ __forceinline__ uint32_t pack_bf2(float a, float b) {
    __nv_bfloat162 t = __floats2bfloat162_rn(a, b);
    return *(uint32_t*)&t;
}

// ---------------------------------------------------------------------------
// K1: FUSED  x->bf16 (smem-resident) + row L2-norm + logits MMA + softmax
//     + VLAD MMA  (one pass over x)
// grid (16 tc, 8 n), 256 threads (8 warps). Block owns rows [n*2048+tc*128, +128).
// ---------------------------------------------------------------------------
__global__ __launch_bounds__(256) void fused_kernel(
        const float* __restrict__ x, const float* __restrict__ W,
        const float* __restrict__ bias) {
    extern __shared__ __align__(16) __nv_bfloat16 sm[];
    __nv_bfloat16 (*xs)[XS_STR] = (__nv_bfloat16 (*)[XS_STR])sm;
    __nv_bfloat16 (*ws)[WS_STR] = (__nv_bfloat16 (*)[WS_STR])(sm + 128 * XS_STR);
    __nv_bfloat16 (*as)[AS_STR] = (__nv_bfloat16 (*)[AS_STR])(sm + 128 * XS_STR + 64 * WS_STR);

    __shared__ float rowinv[128];
    __shared__ float sbias[64];
    __shared__ float sAsum[64];

    const int tid = threadIdx.x;
    const int w   = tid >> 5;
    const int l   = tid & 31;
    const int tc  = blockIdx.x;
    const int n   = blockIdx.y;
    const size_t m0 = (size_t)n * 2048 + tc * 128;

    if (tid < 64) { sbias[tid] = bias[tid]; sAsum[tid] = 0.f; }

    // ---- Phase 1: load + convert (warp-per-16-rows, fully coalesced) ----
    {
        const float4* xg = (const float4*)(x + m0 * 512);
#pragma unroll 2
        for (int rr = 0; rr < 16; rr++) {
            const int r = w * 16 + rr;
            float4 v[4];
#pragma unroll
            for (int cb = 0; cb < 4; cb++)
                v[cb] = xg[(size_t)r * 128 + cb * 32 + l];
            float sq = 0.f;
#pragma unroll
            for (int cb = 0; cb < 4; cb++) {
                sq += v[cb].x * v[cb].x + v[cb].y * v[cb].y
                    + v[cb].z * v[cb].z + v[cb].w * v[cb].w;
                uint2 u = make_uint2(pack_bf2(v[cb].x, v[cb].y),
                                     pack_bf2(v[cb].z, v[cb].w));
                *(uint2*)&xs[r][(cb * 32 + l) * 4] = u;  // single STS.64
            }
            sq += __shfl_xor_sync(~0u, sq, 16);
            sq += __shfl_xor_sync(~0u, sq, 8);
            sq += __shfl_xor_sync(~0u, sq, 4);
            sq += __shfl_xor_sync(~0u, sq, 2);
            sq += __shfl_xor_sync(~0u, sq, 1);
            if (l == 0) rowinv[r] = 1.f / fmaxf(sqrtf(sq), EPSF);
        }
        const float4* wg = (const float4*)W;
#pragma unroll 2
        for (int rr = 0; rr < 8; rr++) {
            const int r = w * 8 + rr;
            float4 v[4];
#pragma unroll
            for (int cb = 0; cb < 4; cb++)
                v[cb] = wg[(size_t)r * 128 + cb * 32 + l];
#pragma unroll
            for (int cb = 0; cb < 4; cb++) {
                uint2 u = make_uint2(pack_bf2(v[cb].x, v[cb].y),
                                     pack_bf2(v[cb].z, v[cb].w));
                *(uint2*)&ws[r][(cb * 32 + l) * 4] = u;
            }
        }
    }
    __syncthreads();

    // ---- Phase 2: logits MMA  C[128 m x 64 k] over D=512 ----
    const int m0w = w * 16;
    const int a_row  = (l & 7) + ((l >> 3) & 1) * 8;
    const int a_koff = (l >> 4) * 8;
    const int b_row  = ((l >> 4) * 8) + (l & 7);
    const int b_koff = ((l >> 3) & 1) * 8;

    float acc[8][4];
#pragma unroll
    for (int i = 0; i < 8; i++)
#pragma unroll
        for (int j = 0; j < 4; j++) acc[i][j] = 0.f;

#pragma unroll 4
    for (int ks = 0; ks < 32; ks++) {
        const int k0 = ks * 16;
        uint32_t a0, a1, a2, a3;
        ldsm_x4(smem_u32(&xs[m0w + a_row][k0 + a_koff]), a0, a1, a2, a3);
#pragma unroll
        for (int nf2 = 0; nf2 < 4; nf2++) {
            uint32_t b0, b1, b2, b3;
            ldsm_x4(smem_u32(&ws[nf2 * 16 + b_row][k0 + b_koff]), b0, b1, b2, b3);
            mma16816(acc[nf2 * 2],     a0, a1, a2, a3, b0, b1);
            mma16816(acc[nf2 * 2 + 1], a0, a1, a2, a3, b2, b3);
        }
    }

    // ---- Phase 3: register softmax (row of 64 lives in 4 lanes sharing g) ----
    {
        const int g  = l >> 2;
        const int c2 = (l & 3) * 2;
        const int r0 = m0w + g, r1 = r0 + 8;
        const float inv0 = rowinv[r0], inv1 = rowinv[r1];

        float L0[16], L1[16];
#pragma unroll
        for (int nf = 0; nf < 8; nf++) {
            const int col = nf * 8 + c2;
            L0[2 * nf]     = acc[nf][0] * inv0 + sbias[col];
            L0[2 * nf + 1] = acc[nf][1] * inv0 + sbias[col + 1];
            L1[2 * nf]     = acc[nf][2] * inv1 + sbias[col];
            L1[2 * nf + 1] = acc[nf][3] * inv1 + sbias[col + 1];
        }
        float mx0 = -1e30f, mx1 = -1e30f;
#pragma unroll
        for (int j = 0; j < 16; j++) { mx0 = fmaxf(mx0, L0[j]); mx1 = fmaxf(mx1, L1[j]); }
        mx0 = fmaxf(mx0, __shfl_xor_sync(~0u, mx0, 1));
        mx0 = fmaxf(mx0, __shfl_xor_sync(~0u, mx0, 2));
        mx1 = fmaxf(mx1, __shfl_xor_sync(~0u, mx1, 1));
        mx1 = fmaxf(mx1, __shfl_xor_sync(~0u, mx1, 2));
        float s0 = 0.f, s1 = 0.f;
#pragma unroll
        for (int j = 0; j < 16; j++) {
            L0[j] = __expf(L0[j] - mx0); s0 += L0[j];
            L1[j] = __expf(L1[j] - mx1); s1 += L1[j];
        }
        s0 += __shfl_xor_sync(~0u, s0, 1); s0 += __shfl_xor_sync(~0u, s0, 2);
        s1 += __shfl_xor_sync(~0u, s1, 1); s1 += __shfl_xor_sync(~0u, s1, 2);
        const float rcp0 = 1.f / s0, rcp1 = 1.f / s1;

        float cs[16];
#pragma unroll
        for (int j = 0; j < 16; j++) {
            L0[j] *= rcp0; L1[j] *= rcp1;          // a values (exact fp32)
            cs[j] = L0[j] + L1[j];
        }
#pragma unroll
        for (int j = 0; j < 16; j++) {
            cs[j] += __shfl_xor_sync(~0u, cs[j], 4);
            cs[j] += __shfl_xor_sync(~0u, cs[j], 8);
            cs[j] += __shfl_xor_sync(~0u, cs[j], 16);
        }
        if (l < 4) {
#pragma unroll
            for (int nf = 0; nf < 8; nf++) {
                const int col = nf * 8 + c2;
                atomicAdd(&sAsum[col],     cs[2 * nf]);        // smem atomics only
                atomicAdd(&sAsum[col + 1], cs[2 * nf + 1]);
            }
        }
#pragma unroll
        for (int nf = 0; nf < 8; nf++) {
            const int col = nf * 8 + c2;
            *(__nv_bfloat162*)&as[r0][col] =
                __floats2bfloat162_rn(L0[2 * nf] * inv0, L0[2 * nf + 1] * inv0);
            *(__nv_bfloat162*)&as[r1][col] =
                __floats2bfloat162_rn(L1[2 * nf] * inv1, L1[2 * nf + 1] * inv1);
        }
    }
    __syncthreads();
    if (tid < 64)  // plain (non-atomic) asum partial store
        g_asump[(tc * 8 + n) * 64 + tid] = sAsum[tid];

    // ---- Phase 4: VLAD MMA  C[64 k x 512 d] = a'^T (64x128) * xs (128x512) ----
    const int wm  = (w & 3) * 16;        // cluster rows
    const int wn2 = (w >> 2) * 64;       // d sub-column within 128-wide tile
    const int at_row = ((l >> 4) * 8) + (l & 7);
    const int at_col = ((l >> 3) & 1) * 8;
    const int bt_row = (((l >> 3) & 1) * 8) + (l & 7);
    const int bt_col = (l >> 4) * 8;

    uint32_t ar[8][4];
#pragma unroll
    for (int ts = 0; ts < 8; ts++)
        ldsm_x4t(smem_u32(&as[ts * 16 + at_row][wm + at_col]),
                 ar[ts][0], ar[ts][1], ar[ts][2], ar[ts][3]);

    const int g  = l >> 2;
    const int c2 = (l & 3) * 2;
    const size_t kn0 = (size_t)n * 64;

#pragma unroll
    for (int dt = 0; dt < 4; dt++) {
        const int dbase = dt * 128 + wn2;
        float vacc[8][4];
#pragma unroll
        for (int i = 0; i < 8; i++)
#pragma unroll
            for (int j = 0; j < 4; j++) vacc[i][j] = 0.f;

#pragma unroll
        for (int ts = 0; ts < 8; ts++) {
            const int kt = ts * 16;
#pragma unroll
            for (int nf2 = 0; nf2 < 4; nf2++) {
                uint32_t b0, b1, b2, b3;
                ldsm_x4t(smem_u32(&xs[kt + bt_row][dbase + nf2 * 16 + bt_col]),
                         b0, b1, b2, b3);
                mma16816(vacc[nf2 * 2],     ar[ts][0], ar[ts][1], ar[ts][2], ar[ts][3], b0, b1);
                mma16816(vacc[nf2 * 2 + 1], ar[ts][0], ar[ts][1], ar[ts][2], ar[ts][3], b2, b3);
            }
        }
        // bf16 partial stores, layout [n][k][p=tc][d]
#pragma unroll
        for (int nf = 0; nf < 8; nf++) {
            const int col = dbase + nf * 8 + c2;
            *(__nv_bfloat162*)&g_vpb[(((kn0 + wm + g) * 16 + tc) << 9) + col] =
                __floats2bfloat162_rn(vacc[nf][0], vacc[nf][1]);
            *(__nv_bfloat162*)&g_vpb[(((kn0 + wm + g + 8) * 16 + tc) << 9) + col] =
                __floats2bfloat162_rn(vacc[nf][2], vacc[nf][3]);
        }
    }
}

// ---------------------------------------------------------------------------
// K2: finalize. 128 blocks x 256 threads, 4 rows per block, 64 threads/row.
//     Each thread owns 8 contiguous d-elements: 16x LDG.128 of bf16 partials,
//     packed bf16x2 HADD2 reduction tree (60 HADD2), single fp32 convert,
//     v -= asum*c, intra L2 norm, analytic global 1/8, write.
// ---------------------------------------------------------------------------
__global__ __launch_bounds__(256) void finalize_kernel(
        const float* __restrict__ cent, float* __restrict__ out) {
    __shared__ float wsum[4][2];
    __shared__ float s_sh[4];

    const int tid = threadIdx.x;
    const int w   = tid >> 5;
    const int l   = tid & 31;
    const int rb  = w >> 1;          // row within block (0..3)
    const int wr  = w & 1;           // warp within row (0..1)
    const int row = blockIdx.x * 4 + rb;   // n*64+k
    const int k   = row & 63;
    const int n   = row >> 6;

    // asum reduce (16 partials) on the first warp of each row
    if (wr == 0) {
        float a = (l < 16) ? g_asump[(l * 8 + n) * 64 + k] : 0.f;
        a += __shfl_xor_sync(~0u, a, 8);
        a += __shfl_xor_sync(~0u, a, 4);
        a += __shfl_xor_sync(~0u, a, 2);
        a += __shfl_xor_sync(~0u, a, 1);
        if (l == 0) s_sh[rb] = a;
    }

    // 16 coalesced LDG.128 of this thread's 8 elements across all partials
    const int ei = wr * 32 + l;                       // uint4 index (8 bf16)
    const uint4* base = (const uint4*)(g_vpb + (size_t)row * 16 * 512);
    uint4 d[16];
#pragma unroll
    for (int p = 0; p < 16; p++) d[p] = base[p * 64 + ei];

    // packed bf16x2 pairwise reduction tree: 15 levels x 4 lanes = 60 HADD2
#pragma unroll
    for (int step = 8; step > 0; step >>= 1)
#pragma unroll
        for (int p = 0; p < 8; p++) {
            if (p < step) {
                d[p].x = bf22u(__hadd2(u2bf2(d[p].x), u2bf2(d[p + step].x)));
                d[p].y = bf22u(__hadd2(u2bf2(d[p].y), u2bf2(d[p + step].y)));
                d[p].z = bf22u(__hadd2(u2bf2(d[p].z), u2bf2(d[p + step].z)));
                d[p].w = bf22u(__hadd2(u2bf2(d[p].w), u2bf2(d[p + step].w)));
            }
        }

    float v[8];
    {
        const float2 f0 = __bfloat1622float2(u2bf2(d[0].x));
        const float2 f1 = __bfloat1622float2(u2bf2(d[0].y));
        const float2 f2 = __bfloat1622float2(u2bf2(d[0].z));
        const float2 f3 = __bfloat1622float2(u2bf2(d[0].w));
        v[0] = f0.x; v[1] = f0.y; v[2] = f1.x; v[3] = f1.y;
        v[4] = f2.x; v[5] = f2.y; v[6] = f3.x; v[7] = f3.y;
    }

    __syncthreads();
    const float s = s_sh[rb];
    const float4 c0 = *(const float4*)(cent + (size_t)k * 512 + ei * 8);
    const float4 c1 = *(const float4*)(cent + (size_t)k * 512 + ei * 8 + 4);
    v[0] -= s * c0.x; v[1] -= s * c0.y; v[2] -= s * c0.z; v[3] -= s * c0.w;
    v[4] -= s * c1.x; v[5] -= s * c1.y; v[6] -= s * c1.z; v[7] -= s * c1.w;

    float sq = 0.f;
#pragma unroll
    for (int j = 0; j < 8; j++) sq += v[j] * v[j];
    sq += __shfl_xor_sync(~0u, sq, 16);
    sq += __shfl_xor_sync(~0u, sq, 8);
    sq += __shfl_xor_sync(~0u, sq, 4);
    sq += __shfl_xor_sync(~0u, sq, 2);
    sq += __shfl_xor_sync(~0u, sq, 1);
    if (l == 0) wsum[rb][wr] = sq;
    __syncthreads();

    const float tot = wsum[rb][0] + wsum[rb][1];
    const float inv = 0.125f / fmaxf(sqrtf(tot), EPSF);  // intra-norm * global 1/8

    float4 o0, o1;
    o0.x = v[0] * inv; o0.y = v[1] * inv; o0.z = v[2] * inv; o0.w = v[3] * inv;
    o1.x = v[4] * inv; o1.y = v[5] * inv; o1.z = v[6] * inv; o1.w = v[7] * inv;
    float* op = out + (size_t)row * 512 + ei * 8;
    *(float4*)op       = o0;
    *(float4*)(op + 4) = o1;
}

// ---------------------------------------------------------------------------
extern "C" void kernel_launch(void* const* d_in, const int* in_sizes, int n_in,
                              void* d_out, int out_size) {
    const float* x    = (const float*)d_in[0];   // [8,2048,512]
    const float* W    = (const float*)d_in[1];   // [64,512]
    const float* b    = (const float*)d_in[2];   // [64]
    const float* cent = (const float*)d_in[3];   // [64,512]
    float* out = (float*)d_out;                  // [8, 64*512]

    cudaFuncSetAttribute(fused_kernel,
                         cudaFuncAttributeMaxDynamicSharedMemorySize,
                         (int)SMEM_BYTES);

    fused_kernel<<<dim3(16, 8), 256, SMEM_BYTES>>>(x, W, b);
    finalize_kernel<<<128, 256>>>(cent, out);
}